// round 5
// baseline (speedup 1.0000x reference)
#include <cuda_runtime.h>

#define D 128
#define MAX_NODES 50048
#define MAX_E     1048576
#define BK 32
#define SAP 132

// Scratch (allocation-free rule: __device__ globals)
__device__ float g_fp[MAX_NODES * D];      // F' = feature @ W^T
__device__ int   g_count[MAX_NODES];
__device__ int   g_start[MAX_NODES + 1];
__device__ int   g_cursor[MAX_NODES];
__device__ int   g_eid[MAX_E];

// ---------------------------------------------------------------------------
// zero per-node edge counts (must precede hist)
// ---------------------------------------------------------------------------
__global__ void zero_count_kernel(int N) {
    int i = blockIdx.x * blockDim.x + threadIdx.x;
    if (i < N) g_count[i] = 0;
}

// ---------------------------------------------------------------------------
// GEMM body: F'[br..br+128) = feature[rows] @ W^T   (no bias/relu here)
// 256 threads, 8x8 microtile, padded k-major smem tiles.
// ---------------------------------------------------------------------------
__device__ __forceinline__ void gemm_body(int br,
                                          const float* __restrict__ A,
                                          const float* __restrict__ Wm,
                                          int M,
                                          float* sA, float* sW) {
    int tid = threadIdx.x;
    int tx = tid & 15;
    int ty = tid >> 4;

    float acc[8][8];
#pragma unroll
    for (int i = 0; i < 8; i++)
#pragma unroll
        for (int j = 0; j < 8; j++) acc[i][j] = 0.f;

    for (int kt = 0; kt < D; kt += BK) {
#pragma unroll
        for (int it = 0; it < 4; it++) {
            int idx4 = tid + it * 256;
            int m  = idx4 >> 3;
            int k  = (idx4 & 7) * 4;

            float4 va = make_float4(0.f, 0.f, 0.f, 0.f);
            if (br + m < M)
                va = *(const float4*)(A + (size_t)(br + m) * D + kt + k);
            sA[(k + 0) * SAP + m] = va.x;
            sA[(k + 1) * SAP + m] = va.y;
            sA[(k + 2) * SAP + m] = va.z;
            sA[(k + 3) * SAP + m] = va.w;

            float4 vw = *(const float4*)(Wm + m * D + kt + k);
            sW[(k + 0) * SAP + m] = vw.x;
            sW[(k + 1) * SAP + m] = vw.y;
            sW[(k + 2) * SAP + m] = vw.z;
            sW[(k + 3) * SAP + m] = vw.w;
        }
        __syncthreads();

#pragma unroll
        for (int k = 0; k < BK; k++) {
            float a[8], wr[8];
            *(float4*)(a)      = *(const float4*)&sA[k * SAP + ty * 8];
            *(float4*)(a + 4)  = *(const float4*)&sA[k * SAP + ty * 8 + 4];
            *(float4*)(wr)     = *(const float4*)&sW[k * SAP + tx * 8];
            *(float4*)(wr + 4) = *(const float4*)&sW[k * SAP + tx * 8 + 4];
#pragma unroll
            for (int i = 0; i < 8; i++)
#pragma unroll
                for (int j = 0; j < 8; j++)
                    acc[i][j] += a[i] * wr[j];
        }
        __syncthreads();
    }

#pragma unroll
    for (int i = 0; i < 8; i++) {
        int m = br + ty * 8 + i;
        if (m < M) {
            float* op = g_fp + (size_t)m * D + tx * 8;
            *(float4*)(op)     = *(const float4*)&acc[i][0];
            *(float4*)(op + 4) = *(const float4*)&acc[i][4];
        }
    }
}

// ---------------------------------------------------------------------------
// Side tasks (4 edges/thread for hist/permute -> MLP=4)
// ---------------------------------------------------------------------------
__device__ __forceinline__ void hist_side(int bid, const int* __restrict__ dst, int E) {
    int base = bid * 1024 + threadIdx.x;
#pragma unroll
    for (int j = 0; j < 4; j++) {
        int e = base + j * 256;
        if (e < E) atomicAdd(&g_count[dst[e]], 1);
    }
}

__device__ __forceinline__ void permute_side(int bid, const int* __restrict__ dst, int E) {
    int base = bid * 1024 + threadIdx.x;
#pragma unroll
    for (int j = 0; j < 4; j++) {
        int e = base + j * 256;
        if (e < E) {
            int pos = atomicAdd(&g_cursor[dst[e]], 1);
            g_eid[pos] = e;
        }
    }
}

// single-block exclusive scan over g_count, 256 threads
__device__ __forceinline__ void scan_side(int N) {
    __shared__ int part[256];
    int t = threadIdx.x;
    int chunk = (N + 255) >> 8;
    int lo = t * chunk;
    int hi = lo + chunk; if (hi > N) hi = N;
    if (lo > N) lo = N;

    int s = 0;
    for (int i = lo; i < hi; i++) s += g_count[i];
    part[t] = s;
    __syncthreads();

    for (int off = 1; off < 256; off <<= 1) {
        int v = part[t];
        int u = (t >= off) ? part[t - off] : 0;
        __syncthreads();
        part[t] = v + u;
        __syncthreads();
    }

    int run = (t == 0) ? 0 : part[t - 1];
    for (int i = lo; i < hi; i++) {
        int c = g_count[i];
        g_start[i]  = run;
        g_cursor[i] = run;
        run += c;
    }
    if (t == 255) g_start[N] = part[255];
}

// ---------------------------------------------------------------------------
// Fused dispatcher: side blocks + a GEMM chunk in one launch.
// stage: 0=hist, 1=scan, 2=permute
// ---------------------------------------------------------------------------
__global__ void __launch_bounds__(256, 2)
fused_kernel(int stage, int n_side, int gemm_base,
             const float* __restrict__ feature,
             const float* __restrict__ Wm,
             const int* __restrict__ dst,
             int M, int E) {
    __shared__ float sA[BK * SAP];
    __shared__ float sW[BK * SAP];

    int bid = blockIdx.x;
    if (bid < n_side) {
        if (stage == 0)      hist_side(bid, dst, E);
        else if (stage == 1) scan_side(M);
        else                 permute_side(bid, dst, E);
    } else {
        gemm_body((gemm_base + bid - n_side) * 128, feature, Wm, M, sA, sW);
    }
}

// ---------------------------------------------------------------------------
// Aggregate + epilogue: one warp per node.
// out[n] = relu(sum_e w_e * F'[src_e] + b), single coalesced 512B store.
// ---------------------------------------------------------------------------
__global__ void aggregate_out_kernel(const int* __restrict__ src,
                                     const float* __restrict__ w,
                                     const float* __restrict__ bias,
                                     float* __restrict__ out,
                                     int N) {
    int t = blockIdx.x * blockDim.x + threadIdx.x;
    int n = t >> 5;
    if (n >= N) return;
    int lane = t & 31;

    int beg = g_start[n];
    int end = g_start[n + 1];

    float4 acc = make_float4(0.f, 0.f, 0.f, 0.f);
    int i = beg;
    for (; i + 1 < end; i += 2) {
        int   e0 = __ldg(&g_eid[i]);
        int   e1 = __ldg(&g_eid[i + 1]);
        int   s0 = __ldg(&src[e0]);
        int   s1 = __ldg(&src[e1]);
        float w0 = __ldg(&w[e0]);
        float w1 = __ldg(&w[e1]);
        float4 v0 = *(const float4*)(g_fp + (size_t)s0 * D + lane * 4);
        float4 v1 = *(const float4*)(g_fp + (size_t)s1 * D + lane * 4);
        acc.x += v0.x * w0 + v1.x * w1;
        acc.y += v0.y * w0 + v1.y * w1;
        acc.z += v0.z * w0 + v1.z * w1;
        acc.w += v0.w * w0 + v1.w * w1;
    }
    if (i < end) {
        int   e0 = __ldg(&g_eid[i]);
        int   s0 = __ldg(&src[e0]);
        float w0 = __ldg(&w[e0]);
        float4 v0 = *(const float4*)(g_fp + (size_t)s0 * D + lane * 4);
        acc.x += v0.x * w0;
        acc.y += v0.y * w0;
        acc.z += v0.z * w0;
        acc.w += v0.w * w0;
    }

    float4 b4 = *(const float4*)(bias + lane * 4);
    acc.x = fmaxf(acc.x + b4.x, 0.f);
    acc.y = fmaxf(acc.y + b4.y, 0.f);
    acc.z = fmaxf(acc.z + b4.z, 0.f);
    acc.w = fmaxf(acc.w + b4.w, 0.f);

    *(float4*)(out + (size_t)n * D + lane * 4) = acc;
}

// ---------------------------------------------------------------------------
// Launch
// ---------------------------------------------------------------------------
extern "C" void kernel_launch(void* const* d_in, const int* in_sizes, int n_in,
                              void* d_out, int out_size) {
    const float* feature = (const float*)d_in[0];
    const int*   src     = (const int*)d_in[1];
    const int*   dst     = (const int*)d_in[2];
    const float* w       = (const float*)d_in[3];
    const float* Wm      = (const float*)d_in[4];
    const float* bias    = (const float*)d_in[5];
    float*       out     = (float*)d_out;

    int M = in_sizes[0] / D;
    int E = in_sizes[1];
    if (E > MAX_E) E = MAX_E;

    int gemm_blocks = (M + 127) / 128;          // 391
    int gA = gemm_blocks / 3;                   // 130
    int gB = gemm_blocks / 3;                   // 130
    int gC = gemm_blocks - gA - gB;             // 131
    int ep_blocks = (E + 1023) / 1024;          // 782

    // K0: zero counts (must precede hist)
    zero_count_kernel<<<(M + 255) / 256, 256>>>(M);

    // K1: hist || gemm chunk A
    fused_kernel<<<ep_blocks + gA, 256>>>(0, ep_blocks, 0, feature, Wm, dst, M, E);

    // K2: scan || gemm chunk B
    fused_kernel<<<1 + gB, 256>>>(1, 1, gA, feature, Wm, dst, M, E);

    // K3: permute || gemm chunk C
    fused_kernel<<<ep_blocks + gC, 256>>>(2, ep_blocks, gA + gB, feature, Wm, dst, M, E);

    // K4: aggregate + bias + relu -> out
    long long agg_threads = (long long)M * 32;
    aggregate_out_kernel<<<(int)((agg_threads + 255) / 256), 256>>>(src, w, bias, out, M);
}

// round 6
// speedup vs baseline: 1.0201x; 1.0201x over previous
#include <cuda_runtime.h>

#define D 128
#define MAX_NODES 50048
#define MAX_E     1048576
#define BK 32
#define SAP 132

// Scratch (allocation-free rule: __device__ globals)
__device__ float g_fp[MAX_NODES * D];      // F' = feature @ W^T
__device__ int   g_count[MAX_NODES];
__device__ int   g_start[MAX_NODES + 1];
__device__ int   g_cursor[MAX_NODES];
__device__ int   g_eid[MAX_E];

// ---------------------------------------------------------------------------
// 1) zero per-node edge counts
// ---------------------------------------------------------------------------
__global__ void zero_count_kernel(int N) {
    int i = blockIdx.x * blockDim.x + threadIdx.x;
    if (i < N) g_count[i] = 0;
}

// ---------------------------------------------------------------------------
// 2) histogram of dst, 4 edges/thread (MLP=4 on the atomics)
// ---------------------------------------------------------------------------
__global__ void hist_kernel(const int* __restrict__ dst, int E) {
    int base = (blockIdx.x * blockDim.x + threadIdx.x) * 4;
    int d0 = -1, d1 = -1, d2 = -1, d3 = -1;
    if (base + 3 < E) {
        d0 = dst[base]; d1 = dst[base + 1]; d2 = dst[base + 2]; d3 = dst[base + 3];
    } else {
        if (base + 0 < E) d0 = dst[base + 0];
        if (base + 1 < E) d1 = dst[base + 1];
        if (base + 2 < E) d2 = dst[base + 2];
        if (base + 3 < E) d3 = dst[base + 3];
    }
    if (d0 >= 0) atomicAdd(&g_count[d0], 1);
    if (d1 >= 0) atomicAdd(&g_count[d1], 1);
    if (d2 >= 0) atomicAdd(&g_count[d2], 1);
    if (d3 >= 0) atomicAdd(&g_count[d3], 1);
}

// ---------------------------------------------------------------------------
// 3) exclusive prefix scan over g_count (single block, 1024 threads)
// ---------------------------------------------------------------------------
__global__ void scan_kernel(int N) {
    __shared__ int part[1024];
    int t = threadIdx.x;
    int chunk = (N + 1023) >> 10;
    int lo = t * chunk;
    int hi = lo + chunk; if (hi > N) hi = N;
    if (lo > N) lo = N;

    int s = 0;
    for (int i = lo; i < hi; i++) s += g_count[i];
    part[t] = s;
    __syncthreads();

    for (int off = 1; off < 1024; off <<= 1) {
        int v = part[t];
        int u = (t >= off) ? part[t - off] : 0;
        __syncthreads();
        part[t] = v + u;
        __syncthreads();
    }

    int run = (t == 0) ? 0 : part[t - 1];
    for (int i = lo; i < hi; i++) {
        int c = g_count[i];
        g_start[i]  = run;
        g_cursor[i] = run;
        run += c;
    }
    if (t == 1023) g_start[N] = part[1023];
}

// ---------------------------------------------------------------------------
// 4) permute: bucket edge ids by dst, 4 edges/thread (MLP=4)
// ---------------------------------------------------------------------------
__global__ void permute_kernel(const int* __restrict__ dst, int E) {
    int base = (blockIdx.x * blockDim.x + threadIdx.x) * 4;
#pragma unroll
    for (int j = 0; j < 4; j++) {
        int e = base + j;
        if (e < E) {
            int pos = atomicAdd(&g_cursor[dst[e]], 1);
            g_eid[pos] = e;
        }
    }
}

// ---------------------------------------------------------------------------
// 5) GEMM: g_fp = feature @ W^T  (fp32 SIMT, 8x8 microtile, no epilogue)
// ---------------------------------------------------------------------------
__global__ void gemm_kernel(const float* __restrict__ A,
                            const float* __restrict__ Wm,
                            int M) {
    __shared__ float sA[BK * SAP];
    __shared__ float sW[BK * SAP];

    int tid = threadIdx.x;
    int tx = tid & 15;
    int ty = tid >> 4;
    int br = blockIdx.x * 128;

    float acc[8][8];
#pragma unroll
    for (int i = 0; i < 8; i++)
#pragma unroll
        for (int j = 0; j < 8; j++) acc[i][j] = 0.f;

    for (int kt = 0; kt < D; kt += BK) {
#pragma unroll
        for (int it = 0; it < 4; it++) {
            int idx4 = tid + it * 256;
            int m  = idx4 >> 3;
            int k  = (idx4 & 7) * 4;

            float4 va = make_float4(0.f, 0.f, 0.f, 0.f);
            if (br + m < M)
                va = *(const float4*)(A + (size_t)(br + m) * D + kt + k);
            sA[(k + 0) * SAP + m] = va.x;
            sA[(k + 1) * SAP + m] = va.y;
            sA[(k + 2) * SAP + m] = va.z;
            sA[(k + 3) * SAP + m] = va.w;

            float4 vw = *(const float4*)(Wm + m * D + kt + k);
            sW[(k + 0) * SAP + m] = vw.x;
            sW[(k + 1) * SAP + m] = vw.y;
            sW[(k + 2) * SAP + m] = vw.z;
            sW[(k + 3) * SAP + m] = vw.w;
        }
        __syncthreads();

#pragma unroll
        for (int k = 0; k < BK; k++) {
            float a[8], wr[8];
            *(float4*)(a)      = *(const float4*)&sA[k * SAP + ty * 8];
            *(float4*)(a + 4)  = *(const float4*)&sA[k * SAP + ty * 8 + 4];
            *(float4*)(wr)     = *(const float4*)&sW[k * SAP + tx * 8];
            *(float4*)(wr + 4) = *(const float4*)&sW[k * SAP + tx * 8 + 4];
#pragma unroll
            for (int i = 0; i < 8; i++)
#pragma unroll
                for (int j = 0; j < 8; j++)
                    acc[i][j] += a[i] * wr[j];
        }
        __syncthreads();
    }

#pragma unroll
    for (int i = 0; i < 8; i++) {
        int m = br + ty * 8 + i;
        if (m < M) {
            float* op = g_fp + (size_t)m * D + tx * 8;
            *(float4*)(op)     = *(const float4*)&acc[i][0];
            *(float4*)(op + 4) = *(const float4*)&acc[i][4];
        }
    }
}

// ---------------------------------------------------------------------------
// 6) Aggregate + epilogue: one warp per node, 4-way unroll (4 outstanding
//    512B row loads). out[n] = relu(sum w_e * F'[src_e] + b).
// ---------------------------------------------------------------------------
__global__ void aggregate_out_kernel(const int* __restrict__ src,
                                     const float* __restrict__ w,
                                     const float* __restrict__ bias,
                                     float* __restrict__ out,
                                     int N) {
    int t = blockIdx.x * blockDim.x + threadIdx.x;
    int n = t >> 5;
    if (n >= N) return;
    int lane = t & 31;

    int beg = g_start[n];
    int end = g_start[n + 1];

    float4 acc = make_float4(0.f, 0.f, 0.f, 0.f);
    int i = beg;
    for (; i + 3 < end; i += 4) {
        int e0 = __ldg(&g_eid[i]);
        int e1 = __ldg(&g_eid[i + 1]);
        int e2 = __ldg(&g_eid[i + 2]);
        int e3 = __ldg(&g_eid[i + 3]);
        int s0 = __ldg(&src[e0]);
        int s1 = __ldg(&src[e1]);
        int s2 = __ldg(&src[e2]);
        int s3 = __ldg(&src[e3]);
        float w0 = __ldg(&w[e0]);
        float w1 = __ldg(&w[e1]);
        float w2 = __ldg(&w[e2]);
        float w3 = __ldg(&w[e3]);
        float4 v0 = *(const float4*)(g_fp + (size_t)s0 * D + lane * 4);
        float4 v1 = *(const float4*)(g_fp + (size_t)s1 * D + lane * 4);
        float4 v2 = *(const float4*)(g_fp + (size_t)s2 * D + lane * 4);
        float4 v3 = *(const float4*)(g_fp + (size_t)s3 * D + lane * 4);
        acc.x += v0.x * w0 + v1.x * w1 + v2.x * w2 + v3.x * w3;
        acc.y += v0.y * w0 + v1.y * w1 + v2.y * w2 + v3.y * w3;
        acc.z += v0.z * w0 + v1.z * w1 + v2.z * w2 + v3.z * w3;
        acc.w += v0.w * w0 + v1.w * w1 + v2.w * w2 + v3.w * w3;
    }
    for (; i < end; i++) {
        int   e0 = __ldg(&g_eid[i]);
        int   s0 = __ldg(&src[e0]);
        float w0 = __ldg(&w[e0]);
        float4 v0 = *(const float4*)(g_fp + (size_t)s0 * D + lane * 4);
        acc.x += v0.x * w0;
        acc.y += v0.y * w0;
        acc.z += v0.z * w0;
        acc.w += v0.w * w0;
    }

    float4 b4 = *(const float4*)(bias + lane * 4);
    acc.x = fmaxf(acc.x + b4.x, 0.f);
    acc.y = fmaxf(acc.y + b4.y, 0.f);
    acc.z = fmaxf(acc.z + b4.z, 0.f);
    acc.w = fmaxf(acc.w + b4.w, 0.f);

    *(float4*)(out + (size_t)n * D + lane * 4) = acc;
}

// ---------------------------------------------------------------------------
// Launch
// ---------------------------------------------------------------------------
extern "C" void kernel_launch(void* const* d_in, const int* in_sizes, int n_in,
                              void* d_out, int out_size) {
    const float* feature = (const float*)d_in[0];
    const int*   src     = (const int*)d_in[1];
    const int*   dst     = (const int*)d_in[2];
    const float* w       = (const float*)d_in[3];
    const float* Wm      = (const float*)d_in[4];
    const float* bias    = (const float*)d_in[5];
    float*       out     = (float*)d_out;

    int M = in_sizes[0] / D;
    int E = in_sizes[1];
    if (E > MAX_E) E = MAX_E;

    zero_count_kernel<<<(M + 255) / 256, 256>>>(M);

    int e4_blocks = (E + 1023) / 1024;
    hist_kernel<<<e4_blocks, 256>>>(dst, E);
    scan_kernel<<<1, 1024>>>(M);
    permute_kernel<<<e4_blocks, 256>>>(dst, E);

    gemm_kernel<<<(M + 127) / 128, 256>>>(feature, Wm, M);

    long long agg_threads = (long long)M * 32;
    aggregate_out_kernel<<<(int)((agg_threads + 255) / 256), 256>>>(src, w, bias, out, M);
}